// round 6
// baseline (speedup 1.0000x reference)
#include <cuda_runtime.h>

#define H 1024
#define T 20
#define GRID 128
#define BLK 512

// Scratch (__device__ globals per alloc-free rule). Fully written before read.
__device__ float g_h1[H];        // enc layer1 output at t=0, batch 4095 == last[0]
__device__ float g_d0[T * H];    // dec layer0 outputs, t-major
__device__ unsigned g_cnt = 0;   // barrier arrival counter (self-resets each use)
__device__ unsigned g_gen = 0;   // barrier generation (monotonic; graph-replay safe)

__device__ __forceinline__ float warp_reduce(float v) {
#pragma unroll
    for (int o = 16; o; o >>= 1) v += __shfl_xor_sync(0xffffffffu, v, o);
    return v;
}

__device__ __forceinline__ void l2_prefetch(const void* p) {
    asm volatile("prefetch.global.L2 [%0];" :: "l"(p));
}

// Sense-reversal grid barrier. GRID=128 <= 148 SMs at 1 block/SM -> all blocks
// co-resident in one wave, spin is deadlock-free. Counter self-resets each use.
__device__ __forceinline__ void grid_barrier() {
    __syncthreads();
    if (threadIdx.x == 0) {
        __threadfence();                                  // release our block's writes
        unsigned gen = *(volatile unsigned*)&g_gen;
        if (atomicAdd(&g_cnt, 1u) == GRID - 1) {
            g_cnt = 0;
            __threadfence();
            atomicAdd(&g_gen, 1u);
        } else {
            while (*(volatile unsigned*)&g_gen == gen) {}
        }
        __threadfence();                                  // acquire others' writes
    }
    __syncthreads();
}

__global__ void __launch_bounds__(BLK, 1) fused_net(
    const float* __restrict__ x,
    const float* __restrict__ enc_w0, const float* __restrict__ enc_b0,
    const float* __restrict__ enc_w1, const float* __restrict__ enc_b1,
    const float* __restrict__ dec_w0, const float* __restrict__ dec_u0,
    const float* __restrict__ dec_b0,
    const float* __restrict__ dec_w1, const float* __restrict__ dec_u1,
    const float* __restrict__ dec_b1,
    const float* __restrict__ out_w, const float* __restrict__ out_b,
    float* __restrict__ out)
{
    __shared__ float s_vec[H];           // staged vector for matvec phases
    __shared__ float s_part[16];         // per-warp partial dot sums
    __shared__ float s_w1[8 * H];        // this block's 8 rows of dec_w1 (32KB)
    __shared__ float s_pre[2][8][T];     // dec1 pre-activation partials (K-halves)

    const int tid = threadIdx.x;
    const int warp = tid >> 5, lane = tid & 31;
    const int row = warp & 7;            // phases 1/2: row index in block
    const int half = warp >> 3;          // phases 1/2: K-half
    const int h = blockIdx.x * 8 + row;

    // L2 prefetch of this block's dec_w1 rows (consumed via smem staging below).
    if (tid < 256)
        l2_prefetch((const char*)(dec_w1 + (size_t)blockIdx.x * 8 * H) + (size_t)tid * 128);

    // ---- Phase 1: h1 = relu(enc_w1 @ relu(enc_w0 @ x[0,4095] + b0) + b1).
    // enc_w1 half-row preloaded BEFORE h0 compute -> DRAM latency overlapped.
    float4 wa, wb, wc, wd;
    {
        const float4* w1p = (const float4*)(enc_w1 + (size_t)h * H) + half * 128;
        wa = __ldg(w1p + lane);
        wb = __ldg(w1p + 32 + lane);
        wc = __ldg(w1p + 64 + lane);
        wd = __ldg(w1p + 96 + lane);
    }
    {
        // x: (20, 4096, 2); x[0, 4095, :] at flat {8190, 8191}. h_{-1}=0 => enc_u unused.
        const float x0 = x[8190], x1 = x[8191];
#pragma unroll
        for (int i = tid; i < H; i += BLK) {
            float v = fmaf(enc_w0[2 * i], x0, fmaf(enc_w0[2 * i + 1], x1, enc_b0[i]));
            s_vec[i] = fmaxf(v, 0.0f);
        }
        __syncthreads();
        const float4* s4 = (const float4*)s_vec + half * 128;
        float4 v0 = s4[lane], v1 = s4[32 + lane], v2 = s4[64 + lane], v3 = s4[96 + lane];
        float acc = 0.0f;
        acc = fmaf(wa.x, v0.x, acc); acc = fmaf(wa.y, v0.y, acc);
        acc = fmaf(wa.z, v0.z, acc); acc = fmaf(wa.w, v0.w, acc);
        acc = fmaf(wb.x, v1.x, acc); acc = fmaf(wb.y, v1.y, acc);
        acc = fmaf(wb.z, v1.z, acc); acc = fmaf(wb.w, v1.w, acc);
        acc = fmaf(wc.x, v2.x, acc); acc = fmaf(wc.y, v2.y, acc);
        acc = fmaf(wc.z, v2.z, acc); acc = fmaf(wc.w, v2.w, acc);
        acc = fmaf(wd.x, v3.x, acc); acc = fmaf(wd.y, v3.y, acc);
        acc = fmaf(wd.z, v3.z, acc); acc = fmaf(wd.w, v3.w, acc);
        acc = warp_reduce(acc);
        if (lane == 0) s_part[warp] = acc;
    }
    // Preload dec_w0 half-row (DRAM latency hides under barrier 1) and stage
    // dec_w1's 8 rows into smem (L2 latency hides under barrier 1 + phase 2).
    {
        const float4* w0p = (const float4*)(dec_w0 + (size_t)h * H) + half * 128;
        wa = __ldg(w0p + lane);
        wb = __ldg(w0p + 32 + lane);
        wc = __ldg(w0p + 64 + lane);
        wd = __ldg(w0p + 96 + lane);
        const float4* w1g = (const float4*)(dec_w1 + (size_t)blockIdx.x * 8 * H);
        float4* w1s = (float4*)s_w1;
#pragma unroll
        for (int j = 0; j < 4; j++)
            w1s[tid * 4 + j] = __ldg(w1g + tid * 4 + j);
    }
    __syncthreads();
    if (tid < 8)
        g_h1[blockIdx.x * 8 + tid] =
            fmaxf(s_part[tid] + s_part[tid + 8] + enc_b1[blockIdx.x * 8 + tid], 0.0f);
    grid_barrier();

    // d_out init (poisoned each replay): block 0 writes out_b into out[0..40)
    // HERE, between barriers 1 and 2; all phase-3 atomics happen after barrier 2,
    // whose fences order these stores before any RMW. 40 outputs, o = t*2+k.
    if (blockIdx.x == 0 && tid < 2 * T) out[tid] = out_b[tid & 1];

    // ---- Phase 2: pre = dec_w0 @ h1 + b; 20-step elementwise IndRNN scan
    //      (time-constant input) -> g_d0. Weights already in registers.
    {
#pragma unroll
        for (int i = tid; i < H; i += BLK) s_vec[i] = g_h1[i];   // coherent
        __syncthreads();
        const float4* s4 = (const float4*)s_vec + half * 128;
        float4 v0 = s4[lane], v1 = s4[32 + lane], v2 = s4[64 + lane], v3 = s4[96 + lane];
        float acc = 0.0f;
        acc = fmaf(wa.x, v0.x, acc); acc = fmaf(wa.y, v0.y, acc);
        acc = fmaf(wa.z, v0.z, acc); acc = fmaf(wa.w, v0.w, acc);
        acc = fmaf(wb.x, v1.x, acc); acc = fmaf(wb.y, v1.y, acc);
        acc = fmaf(wb.z, v1.z, acc); acc = fmaf(wb.w, v1.w, acc);
        acc = fmaf(wc.x, v2.x, acc); acc = fmaf(wc.y, v2.y, acc);
        acc = fmaf(wc.z, v2.z, acc); acc = fmaf(wc.w, v2.w, acc);
        acc = fmaf(wd.x, v3.x, acc); acc = fmaf(wd.y, v3.y, acc);
        acc = fmaf(wd.z, v3.z, acc); acc = fmaf(wd.w, v3.w, acc);
        acc = warp_reduce(acc);
        if (lane == 0) s_part[warp] = acc;
        __syncthreads();
        if (tid < 8) {
            const int g = blockIdx.x * 8 + tid;
            const float pre = s_part[tid] + s_part[tid + 8] + dec_b0[g];
            const float uu = dec_u0[g];
            float d = 0.0f;
#pragma unroll
            for (int t = 0; t < T; t++) {
                d = fmaxf(fmaf(uu, d, pre), 0.0f);
                g_d0[t * H + g] = d;
            }
        }
    }
    grid_barrier();

    // ---- Phase 3: pre1[t][h] = dec_w1[h] . d0[t] + b[h]  (GEMM 20x1024x1024),
    // then dec1 scan fused with the output projection (atomicAdd into out).
    // 16 warps = 2 row-groups(4 rows) x 4 t-quarters x 2 K-halves:
    // 4 rows x 5 t x 512 K per warp. Weights from smem, d0 from global (L1).
    {
        const int kh = warp >> 3;              // K-half
        const int tq = (warp >> 1) & 3;        // t-quarter: t in [tq*5, +5)
        const int rg = warp & 1;               // row-group: rows [rg*4, +4)
        const float4* w4 = (const float4*)s_w1 + rg * 4 * (H / 4) + kh * 128;
        const float4* d04 = (const float4*)g_d0 + tq * 5 * (H / 4) + kh * 128;

        float acc[4][5];
#pragma unroll
        for (int r = 0; r < 4; r++)
#pragma unroll
            for (int t = 0; t < 5; t++) acc[r][t] = 0.0f;

#pragma unroll
        for (int j = 0; j < 4; j++) {
            const int c = j * 32 + lane;
            float4 w0 = w4[c];                 // smem, conflict-free
            float4 w1 = w4[256 + c];
            float4 w2 = w4[512 + c];
            float4 w3 = w4[768 + c];
            float4 v[5];
#pragma unroll
            for (int t = 0; t < 5; t++) v[t] = d04[t * 256 + c];   // coherent
#pragma unroll
            for (int t = 0; t < 5; t++) {
                acc[0][t] = fmaf(w0.x, v[t].x, acc[0][t]); acc[0][t] = fmaf(w0.y, v[t].y, acc[0][t]);
                acc[0][t] = fmaf(w0.z, v[t].z, acc[0][t]); acc[0][t] = fmaf(w0.w, v[t].w, acc[0][t]);
                acc[1][t] = fmaf(w1.x, v[t].x, acc[1][t]); acc[1][t] = fmaf(w1.y, v[t].y, acc[1][t]);
                acc[1][t] = fmaf(w1.z, v[t].z, acc[1][t]); acc[1][t] = fmaf(w1.w, v[t].w, acc[1][t]);
                acc[2][t] = fmaf(w2.x, v[t].x, acc[2][t]); acc[2][t] = fmaf(w2.y, v[t].y, acc[2][t]);
                acc[2][t] = fmaf(w2.z, v[t].z, acc[2][t]); acc[2][t] = fmaf(w2.w, v[t].w, acc[2][t]);
                acc[3][t] = fmaf(w3.x, v[t].x, acc[3][t]); acc[3][t] = fmaf(w3.y, v[t].y, acc[3][t]);
                acc[3][t] = fmaf(w3.z, v[t].z, acc[3][t]); acc[3][t] = fmaf(w3.w, v[t].w, acc[3][t]);
            }
        }
#pragma unroll
        for (int r = 0; r < 4; r++)
#pragma unroll
            for (int t = 0; t < 5; t++) {
                acc[r][t] = warp_reduce(acc[r][t]);
                if (lane == 0) s_pre[kh][rg * 4 + r][tq * 5 + t] = acc[r][t];
            }
        __syncthreads();

        // dec1 scan + fused output projection. out initialized to out_b by
        // block 0 before barrier 2; atomic order only perturbs ~ulp-level sums.
        if (tid < 8) {
            const int hh = blockIdx.x * 8 + tid;
            const float bb = dec_b1[hh], uu = dec_u1[hh];
            const float w0h = out_w[hh];        // out_w[0][hh]
            const float w1h = out_w[H + hh];    // out_w[1][hh]
            float d = 0.0f;
#pragma unroll
            for (int t = 0; t < T; t++) {
                d = fmaxf(fmaf(uu, d, s_pre[0][tid][t] + s_pre[1][tid][t] + bb), 0.0f);
                atomicAdd(out + t * 2, w0h * d);
                atomicAdd(out + t * 2 + 1, w1h * d);
            }
        }
    }
}

extern "C" void kernel_launch(void* const* d_in, const int* in_sizes, int n_in,
                              void* d_out, int out_size) {
    const float* x      = (const float*)d_in[0];
    const float* enc_w0 = (const float*)d_in[1];
    // d_in[2] = enc_u0: unused (only t=0 encoder state needed, h_{-1}=0)
    const float* enc_b0 = (const float*)d_in[3];
    const float* enc_w1 = (const float*)d_in[4];
    // d_in[5] = enc_u1: unused
    const float* enc_b1 = (const float*)d_in[6];
    const float* dec_w0 = (const float*)d_in[7];
    const float* dec_u0 = (const float*)d_in[8];
    const float* dec_b0 = (const float*)d_in[9];
    const float* dec_w1 = (const float*)d_in[10];
    const float* dec_u1 = (const float*)d_in[11];
    const float* dec_b1 = (const float*)d_in[12];
    const float* out_w  = (const float*)d_in[13];
    const float* out_b  = (const float*)d_in[14];
    float* out = (float*)d_out;

    fused_net<<<GRID, BLK>>>(x, enc_w0, enc_b0, enc_w1, enc_b1,
                             dec_w0, dec_u0, dec_b0,
                             dec_w1, dec_u1, dec_b1,
                             out_w, out_b, out);
}

// round 7
// speedup vs baseline: 4.0636x; 4.0636x over previous
#include <cuda_runtime.h>

#define H 1024
#define T 20
#define GRID 128
#define BLK 512

// Scratch (__device__ globals per alloc-free rule). Fully written before read.
__device__ float g_h1[H];        // enc layer1 output at t=0, batch 4095 == last[0]
__device__ float g_d0[T * H];    // dec layer0 outputs, t-major
__device__ unsigned g_cnt = 0;   // barrier arrival counter (self-resets each use)
__device__ unsigned g_gen = 0;   // barrier generation (monotonic; graph-replay safe)

__device__ __forceinline__ float warp_reduce(float v) {
#pragma unroll
    for (int o = 16; o; o >>= 1) v += __shfl_xor_sync(0xffffffffu, v, o);
    return v;
}

__device__ __forceinline__ void l2_prefetch(const void* p) {
    asm volatile("prefetch.global.L2 [%0];" :: "l"(p));
}

// Sense-reversal grid barrier. GRID=128 <= 148 SMs at 1 block/SM -> all blocks
// co-resident in one wave, spin is deadlock-free. Counter self-resets each use.
__device__ __forceinline__ void grid_barrier() {
    __syncthreads();
    if (threadIdx.x == 0) {
        __threadfence();                                  // release our block's writes
        unsigned gen = *(volatile unsigned*)&g_gen;
        if (atomicAdd(&g_cnt, 1u) == GRID - 1) {
            g_cnt = 0;
            __threadfence();
            atomicAdd(&g_gen, 1u);
        } else {
            while (*(volatile unsigned*)&g_gen == gen) {}
        }
        __threadfence();                                  // acquire others' writes
    }
    __syncthreads();
}

__global__ void __launch_bounds__(BLK, 1) fused_net(
    const float* __restrict__ x,
    const float* __restrict__ enc_w0, const float* __restrict__ enc_b0,
    const float* __restrict__ enc_w1, const float* __restrict__ enc_b1,
    const float* __restrict__ dec_w0, const float* __restrict__ dec_u0,
    const float* __restrict__ dec_b0,
    const float* __restrict__ dec_w1, const float* __restrict__ dec_u1,
    const float* __restrict__ dec_b1,
    const float* __restrict__ out_w, const float* __restrict__ out_b,
    float* __restrict__ out)
{
    __shared__ float s_vec[H];       // staged vector for matvec phases
    __shared__ float s_part[16];     // per-warp partial dot sums
    __shared__ float s_pre[8][T];    // dec1 pre-activations for this block's 8 rows
    __shared__ float s_d1[8][T];     // dec1 post-scan outputs (for projection)

    const int tid = threadIdx.x;
    const int warp = tid >> 5, lane = tid & 31;
    const int row = warp & 7;        // phases 1/2: row index in block
    const int half = warp >> 3;      // phases 1/2: K-half
    const int h = blockIdx.x * 8 + row;

    // L2 prefetch of phase-3 weights (dec_w0 is register-preloaded instead).
    if (tid < 256)
        l2_prefetch((const char*)(dec_w1 + (size_t)blockIdx.x * 8 * H) + (size_t)tid * 128);

    // ---- Phase 1: h1 = relu(enc_w1 @ relu(enc_w0 @ x[0,4095] + b0) + b1).
    // enc_w1 half-row preloaded BEFORE h0 compute -> DRAM latency overlapped.
    float4 wa, wb, wc, wd;
    {
        const float4* w1p = (const float4*)(enc_w1 + (size_t)h * H) + half * 128;
        wa = __ldg(w1p + lane);
        wb = __ldg(w1p + 32 + lane);
        wc = __ldg(w1p + 64 + lane);
        wd = __ldg(w1p + 96 + lane);
    }
    {
        // x: (20, 4096, 2); x[0, 4095, :] at flat {8190, 8191}. h_{-1}=0 => enc_u unused.
        const float x0 = x[8190], x1 = x[8191];
#pragma unroll
        for (int i = tid; i < H; i += BLK) {
            float v = fmaf(enc_w0[2 * i], x0, fmaf(enc_w0[2 * i + 1], x1, enc_b0[i]));
            s_vec[i] = fmaxf(v, 0.0f);
        }
        __syncthreads();
        const float4* s4 = (const float4*)s_vec + half * 128;
        float4 v0 = s4[lane], v1 = s4[32 + lane], v2 = s4[64 + lane], v3 = s4[96 + lane];
        float acc = 0.0f;
        acc = fmaf(wa.x, v0.x, acc); acc = fmaf(wa.y, v0.y, acc);
        acc = fmaf(wa.z, v0.z, acc); acc = fmaf(wa.w, v0.w, acc);
        acc = fmaf(wb.x, v1.x, acc); acc = fmaf(wb.y, v1.y, acc);
        acc = fmaf(wb.z, v1.z, acc); acc = fmaf(wb.w, v1.w, acc);
        acc = fmaf(wc.x, v2.x, acc); acc = fmaf(wc.y, v2.y, acc);
        acc = fmaf(wc.z, v2.z, acc); acc = fmaf(wc.w, v2.w, acc);
        acc = fmaf(wd.x, v3.x, acc); acc = fmaf(wd.y, v3.y, acc);
        acc = fmaf(wd.z, v3.z, acc); acc = fmaf(wd.w, v3.w, acc);
        acc = warp_reduce(acc);
        if (lane == 0) s_part[warp] = acc;
    }
    // Preload dec_w0 half-row NOW: its DRAM latency hides under the grid barrier.
    {
        const float4* w0p = (const float4*)(dec_w0 + (size_t)h * H) + half * 128;
        wa = __ldg(w0p + lane);
        wb = __ldg(w0p + 32 + lane);
        wc = __ldg(w0p + 64 + lane);
        wd = __ldg(w0p + 96 + lane);
    }
    __syncthreads();
    if (tid < 8)
        g_h1[blockIdx.x * 8 + tid] =
            fmaxf(s_part[tid] + s_part[tid + 8] + enc_b1[blockIdx.x * 8 + tid], 0.0f);
    grid_barrier();

    // d_out init (poisoned each replay): block 0 writes out_b into out[0..40)
    // between barriers 1 and 2; barrier-2 fences order these stores before any
    // phase-3 atomicAdd from any block. o = t*2+k.
    if (blockIdx.x == 0 && tid < 2 * T) out[tid] = out_b[tid & 1];

    // ---- Phase 2: pre = dec_w0 @ h1 + b; 20-step elementwise IndRNN scan
    //      (time-constant input) -> g_d0. Weights already in registers.
    {
#pragma unroll
        for (int i = tid; i < H; i += BLK) s_vec[i] = g_h1[i];   // coherent
        __syncthreads();
        const float4* s4 = (const float4*)s_vec + half * 128;
        float4 v0 = s4[lane], v1 = s4[32 + lane], v2 = s4[64 + lane], v3 = s4[96 + lane];
        float acc = 0.0f;
        acc = fmaf(wa.x, v0.x, acc); acc = fmaf(wa.y, v0.y, acc);
        acc = fmaf(wa.z, v0.z, acc); acc = fmaf(wa.w, v0.w, acc);
        acc = fmaf(wb.x, v1.x, acc); acc = fmaf(wb.y, v1.y, acc);
        acc = fmaf(wb.z, v1.z, acc); acc = fmaf(wb.w, v1.w, acc);
        acc = fmaf(wc.x, v2.x, acc); acc = fmaf(wc.y, v2.y, acc);
        acc = fmaf(wc.z, v2.z, acc); acc = fmaf(wc.w, v2.w, acc);
        acc = fmaf(wd.x, v3.x, acc); acc = fmaf(wd.y, v3.y, acc);
        acc = fmaf(wd.z, v3.z, acc); acc = fmaf(wd.w, v3.w, acc);
        acc = warp_reduce(acc);
        if (lane == 0) s_part[warp] = acc;
        __syncthreads();
        if (tid < 8) {
            const int g = blockIdx.x * 8 + tid;
            const float pre = s_part[tid] + s_part[tid + 8] + dec_b0[g];
            const float uu = dec_u0[g];
            float d = 0.0f;
#pragma unroll
            for (int t = 0; t < T; t++) {
                d = fmaxf(fmaf(uu, d, pre), 0.0f);
                g_d0[t * H + g] = d;
            }
        }
    }
    grid_barrier();

    // ---- Phase 3: pre1[t][h] = dec_w1[h] . d0[t] + b[h]  (GEMM 20x1024x1024).
    // 16 warps = 4 row-pairs x 4 t-quarters: 2 rows x 5 timesteps per warp
    // (identical to the 17.2us R5 tiling). Then dec1 scan + block-level
    // pre-reduced output projection: ONE atomicAdd per (t,k) per block.
    {
        const int rp = warp & 3;           // row pair within block's 8 rows
        const int tq = warp >> 2;          // t-quarter: t in [tq*5, tq*5+5)
        const int h0 = blockIdx.x * 8 + rp * 2;
        const float4* w0r = (const float4*)(dec_w1 + (size_t)h0 * H);
        const float4* w1r = w0r + (H / 4);
        const float4* d04 = (const float4*)g_d0 + tq * 5 * (H / 4);   // coherent

        float acc0[5], acc1[5];
#pragma unroll
        for (int t = 0; t < 5; t++) { acc0[t] = 0.0f; acc1[t] = 0.0f; }

#pragma unroll
        for (int j = 0; j < 8; j++) {
            const int c = j * 32 + lane;
            float4 a = __ldg(w0r + c);     // weights: kernel-constant, __ldg OK
            float4 q = __ldg(w1r + c);
            float4 v[5];
#pragma unroll
            for (int t = 0; t < 5; t++) v[t] = d04[t * (H / 4) + c];
#pragma unroll
            for (int t = 0; t < 5; t++) {
                acc0[t] = fmaf(a.x, v[t].x, acc0[t]); acc0[t] = fmaf(a.y, v[t].y, acc0[t]);
                acc0[t] = fmaf(a.z, v[t].z, acc0[t]); acc0[t] = fmaf(a.w, v[t].w, acc0[t]);
                acc1[t] = fmaf(q.x, v[t].x, acc1[t]); acc1[t] = fmaf(q.y, v[t].y, acc1[t]);
                acc1[t] = fmaf(q.z, v[t].z, acc1[t]); acc1[t] = fmaf(q.w, v[t].w, acc1[t]);
            }
        }
#pragma unroll
        for (int t = 0; t < 5; t++) {
            acc0[t] = warp_reduce(acc0[t]);
            acc1[t] = warp_reduce(acc1[t]);
        }
        if (lane == 0) {
#pragma unroll
            for (int t = 0; t < 5; t++) s_pre[rp * 2][tq * 5 + t] = acc0[t];
        }
        if (lane == 1) {
#pragma unroll
            for (int t = 0; t < 5; t++) s_pre[rp * 2 + 1][tq * 5 + t] = acc1[t];
        }
        __syncthreads();

        // dec1 scan -> s_d1 (smem), 8 threads.
        if (tid < 8) {
            const int hh = blockIdx.x * 8 + tid;
            const float bb = dec_b1[hh], uu = dec_u1[hh];
            float d = 0.0f;
#pragma unroll
            for (int t = 0; t < T; t++) {
                d = fmaxf(fmaf(uu, d, s_pre[tid][t] + bb), 0.0f);
                s_d1[tid][t] = d;
            }
        }
        __syncthreads();

        // Output projection, block-pre-reduced: 40 threads each fold this
        // block's 8 channels for one (t,k), then a single atomicAdd.
        // Contention: 128 adds/address total across the grid (~3.5K cyc drain).
        if (tid < 2 * T) {
            const int t = tid >> 1, k = tid & 1;
            const float* owr = out_w + (size_t)k * H + blockIdx.x * 8;
            float sum = 0.0f;
#pragma unroll
            for (int ch = 0; ch < 8; ch++)
                sum = fmaf(owr[ch], s_d1[ch][t], sum);
            atomicAdd(out + tid, sum);
        }
    }
}

extern "C" void kernel_launch(void* const* d_in, const int* in_sizes, int n_in,
                              void* d_out, int out_size) {
    const float* x      = (const float*)d_in[0];
    const float* enc_w0 = (const float*)d_in[1];
    // d_in[2] = enc_u0: unused (only t=0 encoder state needed, h_{-1}=0)
    const float* enc_b0 = (const float*)d_in[3];
    const float* enc_w1 = (const float*)d_in[4];
    // d_in[5] = enc_u1: unused
    const float* enc_b1 = (const float*)d_in[6];
    const float* dec_w0 = (const float*)d_in[7];
    const float* dec_u0 = (const float*)d_in[8];
    const float* dec_b0 = (const float*)d_in[9];
    const float* dec_w1 = (const float*)d_in[10];
    const float* dec_u1 = (const float*)d_in[11];
    const float* dec_b1 = (const float*)d_in[12];
    const float* out_w  = (const float*)d_in[13];
    const float* out_b  = (const float*)d_in[14];
    float* out = (float*)d_out;

    fused_net<<<GRID, BLK>>>(x, enc_w0, enc_b0, enc_w1, enc_b1,
                             dec_w0, dec_u0, dec_b0,
                             dec_w1, dec_u1, dec_b1,
                             out_w, out_b, out);
}

// round 8
// speedup vs baseline: 4.1425x; 1.0194x over previous
#include <cuda_runtime.h>

#define H 1024
#define T 20
#define GRID 128
#define BLK 512

// Scratch (__device__ globals per alloc-free rule). Fully written before read.
__device__ float g_h1[H];        // enc layer1 output at t=0, batch 4095 == last[0]
__device__ float g_d0[T * H];    // dec layer0 outputs, t-major
__device__ unsigned g_cnt = 0;   // barrier arrival counter (self-resets each use)
__device__ unsigned g_gen = 0;   // barrier generation (monotonic; graph-replay safe)

__device__ __forceinline__ float warp_reduce(float v) {
#pragma unroll
    for (int o = 16; o; o >>= 1) v += __shfl_xor_sync(0xffffffffu, v, o);
    return v;
}

__device__ __forceinline__ void l2_prefetch(const void* p) {
    asm volatile("prefetch.global.L2 [%0];" :: "l"(p));
}

// Sense-reversal grid barrier. GRID=128 <= 148 SMs at 1 block/SM -> all blocks
// co-resident in one wave, spin is deadlock-free. Counter self-resets each use.
__device__ __forceinline__ void grid_barrier() {
    __syncthreads();
    if (threadIdx.x == 0) {
        __threadfence();                                  // release our block's writes
        unsigned gen = *(volatile unsigned*)&g_gen;
        if (atomicAdd(&g_cnt, 1u) == GRID - 1) {
            g_cnt = 0;
            __threadfence();
            atomicAdd(&g_gen, 1u);
        } else {
            while (*(volatile unsigned*)&g_gen == gen) {}
        }
        __threadfence();                                  // acquire others' writes
    }
    __syncthreads();
}

__global__ void __launch_bounds__(BLK, 1) fused_net(
    const float* __restrict__ x,
    const float* __restrict__ enc_w0, const float* __restrict__ enc_b0,
    const float* __restrict__ enc_w1, const float* __restrict__ enc_b1,
    const float* __restrict__ dec_w0, const float* __restrict__ dec_u0,
    const float* __restrict__ dec_b0,
    const float* __restrict__ dec_w1, const float* __restrict__ dec_u1,
    const float* __restrict__ dec_b1,
    const float* __restrict__ out_w, const float* __restrict__ out_b,
    float* __restrict__ out)
{
    __shared__ float s_vec[H];         // staged vector for matvec phases
    __shared__ float s_part[16];       // per-warp partial dot sums
    __shared__ float s_pre[2][8][T];   // dec1 pre-activation partials (K-halves)
    __shared__ float s_d1[8][T];       // dec1 post-scan outputs (for projection)

    const int tid = threadIdx.x;
    const int warp = tid >> 5, lane = tid & 31;
    const int row = warp & 7;          // phases 1/2: row index in block
    const int half = warp >> 3;        // phases 1/2: K-half
    const int h = blockIdx.x * 8 + row;

    // ---- Phase 1 demand loads FIRST (critical path), prefetch after.
    float4 wa, wb, wc, wd;
    {
        const float4* w1p = (const float4*)(enc_w1 + (size_t)h * H) + half * 128;
        wa = __ldg(w1p + lane);
        wb = __ldg(w1p + 32 + lane);
        wc = __ldg(w1p + 64 + lane);
        wd = __ldg(w1p + 96 + lane);
    }
    // x: (20, 4096, 2); x[0, 4095, :] at flat {8190, 8191}. h_{-1}=0 => enc_u unused.
    const float x0 = x[8190], x1 = x[8191];
#pragma unroll
    for (int i = tid; i < H; i += BLK) {
        float v = fmaf(enc_w0[2 * i], x0, fmaf(enc_w0[2 * i + 1], x1, enc_b0[i]));
        s_vec[i] = fmaxf(v, 0.0f);
    }
    // dec_w1 L2 prefetch AFTER phase-1 demand loads (consumed via register
    // preload in the barrier-2 window below).
    if (tid < 256)
        l2_prefetch((const char*)(dec_w1 + (size_t)blockIdx.x * 8 * H) + (size_t)tid * 128);

    // ---- Phase 1: h1 = relu(enc_w1 @ relu(enc_w0 @ x + b0) + b1).
    {
        __syncthreads();
        const float4* s4 = (const float4*)s_vec + half * 128;
        float4 v0 = s4[lane], v1 = s4[32 + lane], v2 = s4[64 + lane], v3 = s4[96 + lane];
        float acc = 0.0f;
        acc = fmaf(wa.x, v0.x, acc); acc = fmaf(wa.y, v0.y, acc);
        acc = fmaf(wa.z, v0.z, acc); acc = fmaf(wa.w, v0.w, acc);
        acc = fmaf(wb.x, v1.x, acc); acc = fmaf(wb.y, v1.y, acc);
        acc = fmaf(wb.z, v1.z, acc); acc = fmaf(wb.w, v1.w, acc);
        acc = fmaf(wc.x, v2.x, acc); acc = fmaf(wc.y, v2.y, acc);
        acc = fmaf(wc.z, v2.z, acc); acc = fmaf(wc.w, v2.w, acc);
        acc = fmaf(wd.x, v3.x, acc); acc = fmaf(wd.y, v3.y, acc);
        acc = fmaf(wd.z, v3.z, acc); acc = fmaf(wd.w, v3.w, acc);
        acc = warp_reduce(acc);
        if (lane == 0) s_part[warp] = acc;
    }
    // Preload dec_w0 half-row NOW: its DRAM latency hides under barrier 1.
    {
        const float4* w0p = (const float4*)(dec_w0 + (size_t)h * H) + half * 128;
        wa = __ldg(w0p + lane);
        wb = __ldg(w0p + 32 + lane);
        wc = __ldg(w0p + 64 + lane);
        wd = __ldg(w0p + 96 + lane);
    }
    __syncthreads();
    if (tid < 8)
        g_h1[blockIdx.x * 8 + tid] =
            fmaxf(s_part[tid] + s_part[tid + 8] + enc_b1[blockIdx.x * 8 + tid], 0.0f);
    grid_barrier();

    // d_out init (poisoned each replay): block 0 writes out_b into out[0..40)
    // between barriers 1 and 2; barrier-2 fences order these stores before any
    // phase-3 atomicAdd from any block. o = t*2+k.
    if (blockIdx.x == 0 && tid < 2 * T) out[tid] = out_b[tid & 1];

    // Phase-3 warp roles (needed for the weight preload below).
    const int rp = warp & 3;             // row pair: rows [rp*2, rp*2+2)
    const int kh = (warp >> 2) & 1;      // K-half: [kh*512, +512)
    const int th = warp >> 3;            // t-half: t in [th*10, +10)
    const int h0 = blockIdx.x * 8 + rp * 2;

    // ---- Phase 2: pre = dec_w0 @ h1 + b; 20-step elementwise IndRNN scan
    //      (time-constant input) -> g_d0. Weights already in registers.
    float4 w8[8];                        // phase-3 weights: [r*4+j], r in {0,1}
    {
#pragma unroll
        for (int i = tid; i < H; i += BLK) s_vec[i] = g_h1[i];   // coherent
        __syncthreads();
        const float4* s4 = (const float4*)s_vec + half * 128;
        float4 v0 = s4[lane], v1 = s4[32 + lane], v2 = s4[64 + lane], v3 = s4[96 + lane];
        float acc = 0.0f;
        acc = fmaf(wa.x, v0.x, acc); acc = fmaf(wa.y, v0.y, acc);
        acc = fmaf(wa.z, v0.z, acc); acc = fmaf(wa.w, v0.w, acc);
        acc = fmaf(wb.x, v1.x, acc); acc = fmaf(wb.y, v1.y, acc);
        acc = fmaf(wb.z, v1.z, acc); acc = fmaf(wb.w, v1.w, acc);
        acc = fmaf(wc.x, v2.x, acc); acc = fmaf(wc.y, v2.y, acc);
        acc = fmaf(wc.z, v2.z, acc); acc = fmaf(wc.w, v2.w, acc);
        acc = fmaf(wd.x, v3.x, acc); acc = fmaf(wd.y, v3.y, acc);
        acc = fmaf(wd.z, v3.z, acc); acc = fmaf(wd.w, v3.w, acc);
        acc = warp_reduce(acc);
        if (lane == 0) s_part[warp] = acc;

        // Preload phase-3 dec_w1 slice (2 rows x 512 K): L2-warm from the entry
        // prefetch; latency drains under the scan + barrier 2.
        {
            const float4* wb4 = (const float4*)dec_w1 + ((size_t)h0 * H + kh * 512) / 4;
#pragma unroll
            for (int r = 0; r < 2; r++)
#pragma unroll
                for (int j = 0; j < 4; j++)
                    w8[r * 4 + j] = __ldg(wb4 + r * 256 + j * 32 + lane);
        }

        __syncthreads();
        if (tid < 8) {
            const int g = blockIdx.x * 8 + tid;
            const float pre = s_part[tid] + s_part[tid + 8] + dec_b0[g];
            const float uu = dec_u0[g];
            float d = 0.0f;
#pragma unroll
            for (int t = 0; t < T; t++) {
                d = fmaxf(fmaf(uu, d, pre), 0.0f);
                g_d0[t * H + g] = d;
            }
        }
    }
    grid_barrier();

    // ---- Phase 3: pre1[t][h] = dec_w1[h] . d0[t] + b[h]  (GEMM 20x1024x1024).
    // 16 warps = 4 row-pairs x 2 K-halves x 2 t-halves; 2 rows x 10 t x 512 K
    // per warp. Weights already in registers; j-loop is pure {LDG + FMA}.
    {
        const float4* d0b = (const float4*)g_d0 + th * 10 * (H / 4) + kh * 128;

        float acc0[10], acc1[10];
#pragma unroll
        for (int t = 0; t < 10; t++) { acc0[t] = 0.0f; acc1[t] = 0.0f; }

#pragma unroll
        for (int j = 0; j < 4; j++) {
            const int c = j * 32 + lane;
            const float4 a = w8[j];        // row 0 chunk j
            const float4 q = w8[4 + j];    // row 1 chunk j
            float4 v[5];
            // t-batch A: t = 0..4 (bounded v[] keeps regs under the 128 cap)
#pragma unroll
            for (int t = 0; t < 5; t++) v[t] = d0b[t * 256 + c];     // coherent
#pragma unroll
            for (int t = 0; t < 5; t++) {
                acc0[t] = fmaf(a.x, v[t].x, acc0[t]); acc0[t] = fmaf(a.y, v[t].y, acc0[t]);
                acc0[t] = fmaf(a.z, v[t].z, acc0[t]); acc0[t] = fmaf(a.w, v[t].w, acc0[t]);
                acc1[t] = fmaf(q.x, v[t].x, acc1[t]); acc1[t] = fmaf(q.y, v[t].y, acc1[t]);
                acc1[t] = fmaf(q.z, v[t].z, acc1[t]); acc1[t] = fmaf(q.w, v[t].w, acc1[t]);
            }
            // t-batch B: t = 5..9
#pragma unroll
            for (int t = 0; t < 5; t++) v[t] = d0b[(t + 5) * 256 + c];
#pragma unroll
            for (int t = 0; t < 5; t++) {
                acc0[t+5] = fmaf(a.x, v[t].x, acc0[t+5]); acc0[t+5] = fmaf(a.y, v[t].y, acc0[t+5]);
                acc0[t+5] = fmaf(a.z, v[t].z, acc0[t+5]); acc0[t+5] = fmaf(a.w, v[t].w, acc0[t+5]);
                acc1[t+5] = fmaf(q.x, v[t].x, acc1[t+5]); acc1[t+5] = fmaf(q.y, v[t].y, acc1[t+5]);
                acc1[t+5] = fmaf(q.z, v[t].z, acc1[t+5]); acc1[t+5] = fmaf(q.w, v[t].w, acc1[t+5]);
            }
        }
#pragma unroll
        for (int t = 0; t < 10; t++) {
            acc0[t] = warp_reduce(acc0[t]);
            acc1[t] = warp_reduce(acc1[t]);
        }
        if (lane == 0) {
#pragma unroll
            for (int t = 0; t < 10; t++) s_pre[kh][rp * 2][th * 10 + t] = acc0[t];
        }
        if (lane == 1) {
#pragma unroll
            for (int t = 0; t < 10; t++) s_pre[kh][rp * 2 + 1][th * 10 + t] = acc1[t];
        }
        __syncthreads();

        // dec1 scan -> s_d1 (combine K-half partials), 8 threads.
        if (tid < 8) {
            const int hh = blockIdx.x * 8 + tid;
            const float bb = dec_b1[hh], uu = dec_u1[hh];
            float d = 0.0f;
#pragma unroll
            for (int t = 0; t < T; t++) {
                d = fmaxf(fmaf(uu, d, s_pre[0][tid][t] + s_pre[1][tid][t] + bb), 0.0f);
                s_d1[tid][t] = d;
            }
        }
        __syncthreads();

        // Output projection, block-pre-reduced: 40 threads each fold this
        // block's 8 channels for one (t,k), then a single atomicAdd
        // (128 adds/address across the grid -> trivial contention).
        if (tid < 2 * T) {
            const int t = tid >> 1, k = tid & 1;
            const float* owr = out_w + (size_t)k * H + blockIdx.x * 8;
            float sum = 0.0f;
#pragma unroll
            for (int ch = 0; ch < 8; ch++)
                sum = fmaf(owr[ch], s_d1[ch][t], sum);
            atomicAdd(out + tid, sum);
        }
    }
}

extern "C" void kernel_launch(void* const* d_in, const int* in_sizes, int n_in,
                              void* d_out, int out_size) {
    const float* x      = (const float*)d_in[0];
    const float* enc_w0 = (const float*)d_in[1];
    // d_in[2] = enc_u0: unused (only t=0 encoder state needed, h_{-1}=0)
    const float* enc_b0 = (const float*)d_in[3];
    const float* enc_w1 = (const float*)d_in[4];
    // d_in[5] = enc_u1: unused
    const float* enc_b1 = (const float*)d_in[6];
    const float* dec_w0 = (const float*)d_in[7];
    const float* dec_u0 = (const float*)d_in[8];
    const float* dec_b0 = (const float*)d_in[9];
    const float* dec_w1 = (const float*)d_in[10];
    const float* dec_u1 = (const float*)d_in[11];
    const float* dec_b1 = (const float*)d_in[12];
    const float* out_w  = (const float*)d_in[13];
    const float* out_b  = (const float*)d_in[14];
    float* out = (float*)d_out;

    fused_net<<<GRID, BLK>>>(x, enc_w0, enc_b0, enc_w1, enc_b1,
                             dec_w0, dec_u0, dec_b0,
                             dec_w1, dec_u1, dec_b1,
                             out_w, out_b, out);
}